// round 11
// baseline (speedup 1.0000x reference)
#include <cuda_runtime.h>
#include <cuda_fp16.h>
#include <math.h>
#include <stdint.h>

// Problem constants
#define NB   4
#define NT   512
#define NH   512
#define NV   32000
#define NS   512
#define NSDV 300
#define NTDV 512
#define MM   (NB*NT)              // 2048 rows
#define NOUT (NV+NSDV+NTDV)       // 32812
#define KA   1024                 // per-row storage: [hi(512) | lo(512)] f16

// Scratch (static device arrays; no allocation allowed)
__device__ float g_scores[(size_t)MM*NV];         // 262 MB
__device__ float g_p[MM*3];
__device__ float g_sumexp[MM];
__device__ unsigned long long g_amax[MM];
__device__ int   g_done[MM];
__device__ int   g_src_idx[NB*NS];
__device__ int   g_tgt_idx[NB*NT];
__device__ __half g_A2[(size_t)MM*KA];            // 4.2 MB  [m][hi|lo]
__device__ __half g_B2[(size_t)NV*KA];            // 65.5 MB [n][hi|lo] (K-major)

// ---------------------------------------------------------------------------
__device__ __forceinline__ uint32_t smem_u32(const void* p) {
    uint32_t a;
    asm("{ .reg .u64 t; cvta.to.shared.u64 t, %1; cvt.u32.u64 %0, t; }"
        : "=r"(a) : "l"(p));
    return a;
}
__device__ __forceinline__ void cp_async16(uint32_t dst, const void* src) {
    asm volatile("cp.async.cg.shared.global [%0], [%1], 16;"
                 :: "r"(dst), "l"(src));
}
#define CP_COMMIT() asm volatile("cp.async.commit_group;")
#define CP_WAIT1()  asm volatile("cp.async.wait_group 1;")

__device__ __forceinline__ void ldmx4(uint32_t* r, uint32_t addr) {
    asm volatile("ldmatrix.sync.aligned.m8n8.x4.shared.b16 {%0,%1,%2,%3}, [%4];"
                 : "=r"(r[0]), "=r"(r[1]), "=r"(r[2]), "=r"(r[3]) : "r"(addr));
}
// f16 x f16 -> f32 accumulate
__device__ __forceinline__ void mma_f32(float* c, const uint32_t* a,
                                        const uint32_t* b) {
    asm volatile(
        "mma.sync.aligned.m16n8k16.row.col.f32.f16.f16.f32 "
        "{%0,%1,%2,%3}, {%4,%5,%6,%7}, {%8,%9}, {%0,%1,%2,%3};"
        : "+f"(c[0]), "+f"(c[1]), "+f"(c[2]), "+f"(c[3])
        : "r"(a[0]), "r"(a[1]), "r"(a[2]), "r"(a[3]), "r"(b[0]), "r"(b[1]));
}
// f16 x f16 -> f16 accumulate (correction terms)
__device__ __forceinline__ void mma_f16(uint32_t* c, const uint32_t* a,
                                        const uint32_t* b) {
    asm volatile(
        "mma.sync.aligned.m16n8k16.row.col.f16.f16.f16.f16 "
        "{%0,%1}, {%2,%3,%4,%5}, {%6,%7}, {%0,%1};"
        : "+r"(c[0]), "+r"(c[1])
        : "r"(a[0]), "r"(a[1]), "r"(a[2]), "r"(a[3]), "r"(b[0]), "r"(b[1]));
}

// ---------------------------------------------------------------------------
// One-hot index extraction
// ---------------------------------------------------------------------------
__global__ void prep_idx_kernel(const float* __restrict__ smap,
                                const float* __restrict__ tmap) {
    int i = blockIdx.x * blockDim.x + threadIdx.x;   // 0..2047
    if (i >= NB*NS) return;
    {
        const float* r = smap + (size_t)i * NSDV;
        int idx = 0;
        for (int v = 0; v < NSDV; v++) if (r[v] > 0.5f) idx = v;
        g_src_idx[i] = idx;
    }
    {
        const float* r = tmap + (size_t)i * NTDV;
        int idx = 0;
        for (int v = 0; v < NTDV; v++) if (r[v] > 0.5f) idx = v;
        g_tgt_idx[i] = idx;
    }
}

// ---------------------------------------------------------------------------
// Merged: gate p = softmax(h@Wp+bp), A2 = [Ah|Al] f16 split, zero accums.
// One warp per row.
// ---------------------------------------------------------------------------
__global__ void p_conv_kernel(const float* __restrict__ H,
                              const float* __restrict__ Wp,
                              const float* __restrict__ bp) {
    int warp = threadIdx.x >> 5;
    int lane = threadIdx.x & 31;
    int row  = blockIdx.x * 4 + warp;
    if (row >= MM) return;
    const float* h = H + (size_t)row * NH;
    __half* ap = g_A2 + (size_t)row * KA;
    float s0 = 0.f, s1 = 0.f, s2 = 0.f;
    #pragma unroll
    for (int k = lane; k < NH; k += 32) {
        float hv = h[k];
        __half hi = __float2half_rn(hv);
        __half lo = __float2half_rn(hv - __half2float(hi));
        ap[k]      = hi;
        ap[k + NH] = lo;
        s0 = fmaf(hv, Wp[k*3+0], s0);
        s1 = fmaf(hv, Wp[k*3+1], s1);
        s2 = fmaf(hv, Wp[k*3+2], s2);
    }
    #pragma unroll
    for (int o = 16; o > 0; o >>= 1) {
        s0 += __shfl_down_sync(0xffffffff, s0, o);
        s1 += __shfl_down_sync(0xffffffff, s1, o);
        s2 += __shfl_down_sync(0xffffffff, s2, o);
    }
    if (lane == 0) {
        g_sumexp[row] = 0.f;
        g_amax[row]   = 0ull;
        g_done[row]   = 0;
        s0 += bp[0]; s1 += bp[1]; s2 += bp[2];
        float m = fmaxf(s0, fmaxf(s1, s2));
        float e0 = expf(s0 - m), e1 = expf(s1 - m), e2 = expf(s2 - m);
        float inv = 1.0f / (e0 + e1 + e2);
        g_p[row*3+0] = e0 * inv;
        g_p[row*3+1] = e1 * inv;
        g_p[row*3+2] = e2 * inv;
    }
}

// ---------------------------------------------------------------------------
// Transpose Wv [NH][NV] -> B2 [NV][hi(512)|lo(512)] f16
// ---------------------------------------------------------------------------
__global__ void convB_kernel(const float* __restrict__ Wv) {
    __shared__ float t[32][33];
    int n0 = blockIdx.x * 32, k0 = blockIdx.y * 32;
    int tx = threadIdx.x, ty = threadIdx.y;   // block (32, 8)
    #pragma unroll
    for (int i = 0; i < 32; i += 8)
        t[ty+i][tx] = Wv[(size_t)(k0 + ty + i) * NV + n0 + tx];   // t[k][n]
    __syncthreads();
    #pragma unroll
    for (int i = 0; i < 32; i += 8) {
        float v = t[tx][ty+i];                 // k = k0+tx, n = n0+ty+i
        __half hi = __float2half_rn(v);
        __half lo = __float2half_rn(v - __half2float(hi));
        size_t base = (size_t)(n0 + ty + i) * KA + k0 + tx;
        g_B2[base]      = hi;
        g_B2[base + NH] = lo;
    }
}

// ---------------------------------------------------------------------------
// Split-precision GEMM: main term f32-acc, corrections f16-acc.
// CTA 128x64, BK=32 (original K), 8 warps of 32x32, 3-stage cp.async.
// Stage: Ah 8K | Al 8K | Bh 4K | Bl 4K = 24 KB (64B rows, XOR-16B swizzle).
// ---------------------------------------------------------------------------
#define BM 128
#define BN 64
#define BK 32
#define NKITER  (NH/BK)        // 16
#define OFF_AL  8192
#define OFF_BH  16384
#define OFF_BL  20480
#define STAGE_B 24576
#define SMEM_GEMM (3*STAGE_B)  // 72 KB

__global__ __launch_bounds__(256, 2)
void gemm_mma_kernel(const float* __restrict__ bias) {
    extern __shared__ char smem[];
    const uint32_t sb = smem_u32(smem);
    const int tid  = threadIdx.x;
    const int w    = tid >> 5;
    const int lane = tid & 31;
    const int bm   = blockIdx.y * BM;    // 16
    const int bn   = blockIdx.x * BN;    // 500
    const int wm   = w & 3;              // warp row (4): 32 M
    const int wn   = w >> 2;             // warp col (2): 32 N

    float    acc [2][4][4];              // main (f32)
    uint32_t acch[2][4][2];              // corrections (f16x2)
    #pragma unroll
    for (int i = 0; i < 2; i++)
        #pragma unroll
        for (int j = 0; j < 4; j++) {
            #pragma unroll
            for (int q = 0; q < 4; q++) acc[i][j][q] = 0.f;
            acch[i][j][0] = 0u; acch[i][j][1] = 0u;
        }

    // --- loader state: 6 x 16B chunks per thread per stage ---
    const int lr = tid >> 2;             // 0..63
    const int lc = tid & 3;              // 16B chunk within 64B row
    const __half* aptr = g_A2 + (size_t)(bm + lr) * KA + lc * 8;   // hi; lo at +NH
    const __half* bptr = g_B2 + (size_t)(bn + lr) * KA + lc * 8;
    const uint32_t swA0 = (uint32_t)lr * 64 + (uint32_t)((lc ^ (lr & 3)) * 16);
    const uint32_t swA1 = swA0 + 64u * 64u;   // row lr+64 ((row&3) unchanged)

#define LOAD_STAGE(s) do {                                                      \
    uint32_t d = sb + (uint32_t)(s) * STAGE_B;                                  \
    cp_async16(d + swA0,           aptr);                                       \
    cp_async16(d + swA1,           aptr + (size_t)64 * KA);                     \
    cp_async16(d + OFF_AL + swA0,  aptr + NH);                                  \
    cp_async16(d + OFF_AL + swA1,  aptr + (size_t)64 * KA + NH);                \
    cp_async16(d + OFF_BH + swA0,  bptr);                                       \
    cp_async16(d + OFF_BL + swA0,  bptr + NH);                                  \
    CP_COMMIT();                                                                \
    aptr += BK; bptr += BK;                                                     \
} while (0)

    // --- ldmatrix bases (64B-row swizzle) ---
    const uint32_t lnx = (uint32_t)(lane >> 4);   // 16B-chunk low bit
    uint32_t rp_a[2], rp_b[2];
    #pragma unroll
    for (int i = 0; i < 2; i++) {
        int row = wm * 32 + i * 16 + (lane & 15);
        rp_a[i] = (uint32_t)row * 64 + (uint32_t)(((lnx ^ (uint32_t)(row & 3)) & 3) * 16);
    }
    #pragma unroll
    for (int jj = 0; jj < 2; jj++) {
        int row = wn * 32 + jj * 16 + (lane & 15);
        rp_b[jj] = (uint32_t)row * 64 + (uint32_t)(((lnx ^ (uint32_t)(row & 3)) & 3) * 16);
    }

    LOAD_STAGE(0);
    LOAD_STAGE(1);

    for (int kt = 0; kt < NKITER; kt++) {
        const int s = kt % 3;
        CP_WAIT1();
        __syncthreads();
        if (kt + 2 < NKITER) LOAD_STAGE((kt + 2) % 3);

        const uint32_t base = sb + (uint32_t)s * STAGE_B;
        #pragma unroll
        for (int ks = 0; ks < 2; ks++) {
            const uint32_t kx = (uint32_t)ks << 5;   // toggles 16B-chunk bit 1
            uint32_t ah[2][4], al[2][4];
            #pragma unroll
            for (int i = 0; i < 2; i++) {
                ldmx4(ah[i], base + (rp_a[i] ^ kx));
                ldmx4(al[i], base + OFF_AL + (rp_a[i] ^ kx));
            }
            uint32_t bh[4][2], bl[4][2];
            #pragma unroll
            for (int jj = 0; jj < 2; jj++) {
                uint32_t r[4];
                ldmx4(r, base + OFF_BH + (rp_b[jj] ^ kx));
                bh[2*jj][0]   = r[0]; bh[2*jj][1]   = r[2];
                bh[2*jj+1][0] = r[1]; bh[2*jj+1][1] = r[3];
                ldmx4(r, base + OFF_BL + (rp_b[jj] ^ kx));
                bl[2*jj][0]   = r[0]; bl[2*jj][1]   = r[2];
                bl[2*jj+1][0] = r[1]; bl[2*jj+1][1] = r[3];
            }
            #pragma unroll
            for (int i = 0; i < 2; i++)
                #pragma unroll
                for (int j = 0; j < 4; j++) {
                    mma_f32(acc[i][j],  ah[i], bh[j]);   // main
                    mma_f16(acch[i][j], ah[i], bl[j]);   // Ah*Bl
                    mma_f16(acch[i][j], al[i], bh[j]);   // Al*Bh
                }
        }
    }

    // epilogue: merge corrections, bias add, store, per-row partial sumexp
    #pragma unroll
    for (int i = 0; i < 2; i++) {
        const int row = bm + wm * 32 + i * 16 + (lane >> 2);
        float s0 = 0.f, s1 = 0.f;       // rows row, row+8
        #pragma unroll
        for (int j = 0; j < 4; j++) {
            const int col = bn + wn * 32 + j * 8 + (lane & 3) * 2;
            const float b0 = bias[col], b1 = bias[col + 1];
            __half2 h0 = *(__half2*)&acch[i][j][0];   // (r,c),(r,c+1)
            __half2 h1 = *(__half2*)&acch[i][j][1];   // (r+8,c),(r+8,c+1)
            float v00 = acc[i][j][0] + __low2float(h0)  + b0;
            float v01 = acc[i][j][1] + __high2float(h0) + b1;
            float v10 = acc[i][j][2] + __low2float(h1)  + b0;
            float v11 = acc[i][j][3] + __high2float(h1) + b1;
            *(float2*)(g_scores + (size_t)row * NV + col)       = make_float2(v00, v01);
            *(float2*)(g_scores + (size_t)(row + 8) * NV + col) = make_float2(v10, v11);
            s0 += ((col == 0) ? 0.f : __expf(v00)) + __expf(v01);
            s1 += ((col == 0) ? 0.f : __expf(v10)) + __expf(v11);
        }
        s0 += __shfl_xor_sync(0xffffffff, s0, 1);
        s0 += __shfl_xor_sync(0xffffffff, s0, 2);
        s1 += __shfl_xor_sync(0xffffffff, s1, 1);
        s1 += __shfl_xor_sync(0xffffffff, s1, 2);
        if ((lane & 3) == 0) {
            atomicAdd(&g_sumexp[row],     s0);
            atomicAdd(&g_sumexp[row + 8], s1);
        }
    }
}

// ---------------------------------------------------------------------------
// Finalize: 2 blocks per row (vocab halves); copy regions on half 1.
// Streaming loads/stores; argmax via packed u64 atomicMax; last block
// of each row writes the prediction (fused pred).
// ---------------------------------------------------------------------------
__global__ __launch_bounds__(256)
void finalize_kernel(const float* __restrict__ satt,
                     const float* __restrict__ tatt,
                     float* __restrict__ out) {
    const int row  = blockIdx.y;
    const int half = blockIdx.x;
    const int b    = row / NT;
    const int tid  = threadIdx.x;

    __shared__ float red[256];
    __shared__ int   redi[256];
    __shared__ float src_acc[NSDV];
    __shared__ float tgt_acc[NTDV];

    const float pg    = g_p[row*3+2];
    const float scale = pg / g_sumexp[row];

    float* orow = out + (size_t)row * NOUT;
    float  bmax = -1.f;
    int    bidx = 0;

    if (half == 1) {
        const float pcs = g_p[row*3+0];
        const float pct = g_p[row*3+1];
        for (int i = tid; i < NSDV; i += 256) src_acc[i] = 0.f;
        for (int i = tid; i < NTDV; i += 256) tgt_acc[i] = 0.f;
        __syncthreads();
        for (int s = tid; s < NS; s += 256)
            atomicAdd(&src_acc[g_src_idx[b*NS + s]], satt[(size_t)row*NS + s]);
        for (int n = tid; n < NT; n += 256)
            atomicAdd(&tgt_acc[g_tgt_idx[b*NT + n]], tatt[(size_t)row*NTDV + n]);
        __syncthreads();
        for (int v = tid; v < NSDV; v += 256) {
            float pv = pcs * src_acc[v];
            __stcs(&orow[NV + v], pv);
            int gi = NV + v;
            if (pv > bmax || (pv == bmax && gi < bidx)) { bmax = pv; bidx = gi; }
        }
        for (int v = tid; v < NTDV; v += 256) {
            float pv = pct * tgt_acc[v];
            __stcs(&orow[NV + NSDV + v], pv);
            int gi = NV + NSDV + v;
            if (pv > bmax || (pv == bmax && gi < bidx)) { bmax = pv; bidx = gi; }
        }
    }

    const float4* srow4 = (const float4*)(g_scores + (size_t)row * NV);
    float4* orow4 = (float4*)orow;
    const int i0 = half * (NV/8);        // in float4 units
    for (int i = i0 + tid; i < i0 + NV/8; i += 256) {
        float4 v = __ldcs(&srow4[i]);
        float4 p;
        p.x = __expf(v.x) * scale;
        p.y = __expf(v.y) * scale;
        p.z = __expf(v.z) * scale;
        p.w = __expf(v.w) * scale;
        if (i == 0) p.x = 0.f;
        __stcs(&orow4[i], p);
        int base = i * 4;
        if (p.x > bmax) { bmax = p.x; bidx = base;   }
        if (p.y > bmax) { bmax = p.y; bidx = base+1; }
        if (p.z > bmax) { bmax = p.z; bidx = base+2; }
        if (p.w > bmax) { bmax = p.w; bidx = base+3; }
    }

    red[tid]  = bmax;
    redi[tid] = bidx;
    __syncthreads();
    for (int o = 128; o > 0; o >>= 1) {
        if (tid < o) {
            float v2 = red[tid + o]; int i2 = redi[tid + o];
            if (v2 > red[tid] || (v2 == red[tid] && i2 < redi[tid])) {
                red[tid] = v2; redi[tid] = i2;
            }
        }
        __syncthreads();
    }
    if (tid == 0) {
        unsigned long long pk =
            ((unsigned long long)__float_as_uint(red[0]) << 32)
            | (unsigned long long)(0xFFFFFFFFu - (uint32_t)redi[0]);
        atomicMax(&g_amax[row], pk);
        __threadfence();
        int prev = atomicAdd(&g_done[row], 1);
        if (prev == 1) {   // last block for this row: publish prediction
            unsigned long long v = atomicAdd(&g_amax[row], 0ull);
            out[(size_t)MM * NOUT + row] =
                (float)(0xFFFFFFFFu - (uint32_t)v);
        }
    }
}

// ---------------------------------------------------------------------------
extern "C" void kernel_launch(void* const* d_in, const int* in_sizes, int n_in,
                              void* d_out, int out_size) {
    const float* hiddens = (const float*)d_in[0];
    const float* Wp      = (const float*)d_in[1];
    const float* bp      = (const float*)d_in[2];
    const float* Wv      = (const float*)d_in[3];
    const float* bv      = (const float*)d_in[4];
    const float* satt    = (const float*)d_in[5];
    const float* smap    = (const float*)d_in[6];
    const float* tatt    = (const float*)d_in[7];
    const float* tmap    = (const float*)d_in[8];
    float* out = (float*)d_out;

    cudaFuncSetAttribute(gemm_mma_kernel,
                         cudaFuncAttributeMaxDynamicSharedMemorySize, SMEM_GEMM);

    // gemm in launch slot 4 -> gets ncu-captured
    convB_kernel<<<dim3(NV/32, NH/32), dim3(32, 8)>>>(Wv);       // 1
    p_conv_kernel<<<MM/4, 128>>>(hiddens, Wp, bp);               // 2
    prep_idx_kernel<<<8, 256>>>(smap, tmap);                     // 3
    gemm_mma_kernel<<<dim3(NV/BN, MM/BM), 256, SMEM_GEMM>>>(bv); // 4
    finalize_kernel<<<dim3(2, MM), 256>>>(satt, tatt, out);      // 5
}

// round 12
// speedup vs baseline: 1.1387x; 1.1387x over previous
#include <cuda_runtime.h>
#include <cuda_bf16.h>
#include <math.h>
#include <stdint.h>

// Problem constants
#define NB   4
#define NT   512
#define NH   512
#define NV   32000
#define NS   512
#define NSDV 300
#define NTDV 512
#define MM   (NB*NT)              // 2048 rows
#define NOUT (NV+NSDV+NTDV)       // 32812
#define KK   (3*NH)               // 1536 expanded K (Ah|Ah|Al x Bh|Bl|Bh)

// Scratch (static device arrays; no allocation allowed)
__device__ float g_scores[(size_t)MM*NV];         // 262 MB
__device__ float g_p[MM*3];
__device__ float g_sumexp[MM];
__device__ unsigned long long g_amax[MM];
__device__ int   g_done[MM];
__device__ int   g_src_idx[NB*NS];
__device__ int   g_tgt_idx[NB*NT];
__device__ __nv_bfloat16 g_Ap[(size_t)MM*KK];     // 6.3 MB  [m][k']
__device__ __nv_bfloat16 g_Bp[(size_t)NV*KK];     // 98 MB   [n][k'] (K-major)

// ---------------------------------------------------------------------------
__device__ __forceinline__ uint32_t smem_u32(const void* p) {
    uint32_t a;
    asm("{ .reg .u64 t; cvta.to.shared.u64 t, %1; cvt.u32.u64 %0, t; }"
        : "=r"(a) : "l"(p));
    return a;
}
__device__ __forceinline__ void cp_async16(uint32_t dst, const void* src) {
    asm volatile("cp.async.cg.shared.global [%0], [%1], 16;"
                 :: "r"(dst), "l"(src));
}
#define CP_COMMIT() asm volatile("cp.async.commit_group;")
#define CP_WAIT1()  asm volatile("cp.async.wait_group 1;")

__device__ __forceinline__ void ldmx4(uint32_t* r, uint32_t addr) {
    asm volatile("ldmatrix.sync.aligned.m8n8.x4.shared.b16 {%0,%1,%2,%3}, [%4];"
                 : "=r"(r[0]), "=r"(r[1]), "=r"(r[2]), "=r"(r[3]) : "r"(addr));
}
__device__ __forceinline__ void mma16816(float* c, const uint32_t* a,
                                         const uint32_t* b) {
    asm volatile(
        "mma.sync.aligned.m16n8k16.row.col.f32.bf16.bf16.f32 "
        "{%0,%1,%2,%3}, {%4,%5,%6,%7}, {%8,%9}, {%0,%1,%2,%3};"
        : "+f"(c[0]), "+f"(c[1]), "+f"(c[2]), "+f"(c[3])
        : "r"(a[0]), "r"(a[1]), "r"(a[2]), "r"(a[3]), "r"(b[0]), "r"(b[1]));
}

// ---------------------------------------------------------------------------
// One-hot index extraction
// ---------------------------------------------------------------------------
__global__ void prep_idx_kernel(const float* __restrict__ smap,
                                const float* __restrict__ tmap) {
    int i = blockIdx.x * blockDim.x + threadIdx.x;   // 0..2047
    if (i >= NB*NS) return;
    {
        const float* r = smap + (size_t)i * NSDV;
        int idx = 0;
        for (int v = 0; v < NSDV; v++) if (r[v] > 0.5f) idx = v;
        g_src_idx[i] = idx;
    }
    {
        const float* r = tmap + (size_t)i * NTDV;
        int idx = 0;
        for (int v = 0; v < NTDV; v++) if (r[v] > 0.5f) idx = v;
        g_tgt_idx[i] = idx;
    }
}

// ---------------------------------------------------------------------------
// Merged: 3-way gate p = softmax(h@Wp+bp), A' = [Ah|Ah|Al] build,
// zero g_sumexp / g_amax / g_done. One warp per row.
// ---------------------------------------------------------------------------
__global__ void p_conv_kernel(const float* __restrict__ H,
                              const float* __restrict__ Wp,
                              const float* __restrict__ bp) {
    int warp = threadIdx.x >> 5;
    int lane = threadIdx.x & 31;
    int row  = blockIdx.x * 4 + warp;
    if (row >= MM) return;
    const float* h = H + (size_t)row * NH;
    __nv_bfloat16* ap = g_Ap + (size_t)row * KK;
    float s0 = 0.f, s1 = 0.f, s2 = 0.f;
    #pragma unroll
    for (int k = lane; k < NH; k += 32) {
        float hv = h[k];
        __nv_bfloat16 hi = __float2bfloat16(hv);
        __nv_bfloat16 lo = __float2bfloat16(hv - __bfloat162float(hi));
        ap[k]        = hi;
        ap[k + NH]   = hi;
        ap[k + 2*NH] = lo;
        s0 = fmaf(hv, Wp[k*3+0], s0);
        s1 = fmaf(hv, Wp[k*3+1], s1);
        s2 = fmaf(hv, Wp[k*3+2], s2);
    }
    #pragma unroll
    for (int o = 16; o > 0; o >>= 1) {
        s0 += __shfl_down_sync(0xffffffff, s0, o);
        s1 += __shfl_down_sync(0xffffffff, s1, o);
        s2 += __shfl_down_sync(0xffffffff, s2, o);
    }
    if (lane == 0) {
        g_sumexp[row] = 0.f;
        g_amax[row]   = 0ull;
        g_done[row]   = 0;
        s0 += bp[0]; s1 += bp[1]; s2 += bp[2];
        float m = fmaxf(s0, fmaxf(s1, s2));
        float e0 = expf(s0 - m), e1 = expf(s1 - m), e2 = expf(s2 - m);
        float inv = 1.0f / (e0 + e1 + e2);
        g_p[row*3+0] = e0 * inv;
        g_p[row*3+1] = e1 * inv;
        g_p[row*3+2] = e2 * inv;
    }
}

// ---------------------------------------------------------------------------
// Transpose Wv [NH][NV] -> B' [NV][K'] = [Bh | Bl | Bh]
// ---------------------------------------------------------------------------
__global__ void convB_kernel(const float* __restrict__ Wv) {
    __shared__ float t[32][33];
    int n0 = blockIdx.x * 32, k0 = blockIdx.y * 32;
    int tx = threadIdx.x, ty = threadIdx.y;   // block (32, 8)
    #pragma unroll
    for (int i = 0; i < 32; i += 8)
        t[ty+i][tx] = Wv[(size_t)(k0 + ty + i) * NV + n0 + tx];   // t[k][n]
    __syncthreads();
    #pragma unroll
    for (int i = 0; i < 32; i += 8) {
        float v = t[tx][ty+i];                 // k = k0+tx, n = n0+ty+i
        __nv_bfloat16 hi = __float2bfloat16(v);
        __nv_bfloat16 lo = __float2bfloat16(v - __bfloat162float(hi));
        size_t base = (size_t)(n0 + ty + i) * KK + k0 + tx;
        g_Bp[base]        = hi;
        g_Bp[base + NH]   = lo;
        g_Bp[base + 2*NH] = hi;
    }
}

// ---------------------------------------------------------------------------
// mma.sync GEMM (best-known R7 config): 128x128 tiles, BK=64, 3-stage
// cp.async pipeline, 8 warps of 32x64, strength-reduced addressing,
// fused per-row partial sumexp. 2 CTAs/SM.
// ---------------------------------------------------------------------------
#define BM 128
#define BN 128
#define BK 64
#define NKITER (KK/BK)        // 24
#define STAGE_B 32768         // A tile 16KB + B tile 16KB
#define SMEM_GEMM (3*STAGE_B) // 96 KB

__global__ __launch_bounds__(256, 2)
void gemm_mma_kernel(const float* __restrict__ bias) {
    extern __shared__ char smem[];
    const uint32_t sb = smem_u32(smem);
    const int tid  = threadIdx.x;
    const int w    = tid >> 5;
    const int lane = tid & 31;
    const int bm   = blockIdx.y * BM;    // 16
    const int bn   = blockIdx.x * BN;    // 250
    const int wm   = w & 3;              // warp row (4)
    const int wn   = w >> 2;             // warp col (2)

    float acc[2][8][4];
    #pragma unroll
    for (int i = 0; i < 2; i++)
        #pragma unroll
        for (int j = 0; j < 8; j++)
            #pragma unroll
            for (int q = 0; q < 4; q++) acc[i][j][q] = 0.f;

    // --- strength-reduced loader state ---
    const int lr = tid >> 3;             // 0..31
    const int lc = tid & 7;              // 16B chunk
    const __nv_bfloat16* aptr = g_Ap + (size_t)(bm + lr) * KK + lc * 8;
    const __nv_bfloat16* bptr = g_Bp + (size_t)(bn + lr) * KK + lc * 8;
    const uint32_t sw0 = (uint32_t)lr * 128 + (uint32_t)((lc ^ (lr & 7)) * 16);

#define LOAD_STAGE(s) do {                                                      \
    uint32_t d = sb + (uint32_t)(s) * STAGE_B + sw0;                            \
    _Pragma("unroll")                                                           \
    for (int i = 0; i < 4; i++) {                                               \
        cp_async16(d + i * 4096,         aptr + (size_t)i * 32 * KK);           \
        cp_async16(d + 16384 + i * 4096, bptr + (size_t)i * 32 * KK);           \
    }                                                                           \
    CP_COMMIT();                                                                \
    aptr += BK; bptr += BK;                                                     \
} while (0)

    // --- strength-reduced ldmatrix bases ---
    const uint32_t lnx = (uint32_t)(lane >> 4) * 16;
    uint32_t rp_a[2], rp_b[4];
    #pragma unroll
    for (int i = 0; i < 2; i++) {
        int row = wm * 32 + i * 16 + (lane & 15);
        rp_a[i] = (uint32_t)row * 128 + (lnx ^ (uint32_t)((row & 7) * 16));
    }
    #pragma unroll
    for (int jj = 0; jj < 4; jj++) {
        int row = wn * 64 + jj * 16 + (lane & 15);
        rp_b[jj] = (uint32_t)row * 128 + (lnx ^ (uint32_t)((row & 7) * 16));
    }

    LOAD_STAGE(0);
    LOAD_STAGE(1);

    for (int kt = 0; kt < NKITER; kt++) {
        const int s = kt % 3;
        CP_WAIT1();
        __syncthreads();
        if (kt + 2 < NKITER) LOAD_STAGE((kt + 2) % 3);

        const uint32_t abase = sb + (uint32_t)s * STAGE_B;
        const uint32_t bbase = abase + 16384;
        #pragma unroll
        for (int ks = 0; ks < 4; ks++) {
            const uint32_t kx = (uint32_t)ks << 5;
            uint32_t a[2][4];
            #pragma unroll
            for (int i = 0; i < 2; i++)
                ldmx4(a[i], abase + (rp_a[i] ^ kx));
            uint32_t b[8][2];
            #pragma unroll
            for (int jj = 0; jj < 4; jj++) {
                uint32_t r[4];
                ldmx4(r, bbase + (rp_b[jj] ^ kx));
                b[2*jj][0]   = r[0]; b[2*jj][1]   = r[2];
                b[2*jj+1][0] = r[1]; b[2*jj+1][1] = r[3];
            }
            #pragma unroll
            for (int i = 0; i < 2; i++)
                #pragma unroll
                for (int j = 0; j < 8; j++)
                    mma16816(acc[i][j], a[i], b[j]);
        }
    }

    // epilogue: bias add, store scores, per-row partial sum of exp
    #pragma unroll
    for (int i = 0; i < 2; i++) {
        const int row = bm + wm * 32 + i * 16 + (lane >> 2);
        float s0 = 0.f, s1 = 0.f;       // rows row, row+8
        #pragma unroll
        for (int j = 0; j < 8; j++) {
            const int col = bn + wn * 64 + j * 8 + (lane & 3) * 2;
            const float b0 = bias[col], b1 = bias[col + 1];
            float v00 = acc[i][j][0] + b0, v01 = acc[i][j][1] + b1;
            float v10 = acc[i][j][2] + b0, v11 = acc[i][j][3] + b1;
            *(float2*)(g_scores + (size_t)row * NV + col)       = make_float2(v00, v01);
            *(float2*)(g_scores + (size_t)(row + 8) * NV + col) = make_float2(v10, v11);
            s0 += ((col == 0) ? 0.f : __expf(v00)) + __expf(v01);
            s1 += ((col == 0) ? 0.f : __expf(v10)) + __expf(v11);
        }
        s0 += __shfl_xor_sync(0xffffffff, s0, 1);
        s0 += __shfl_xor_sync(0xffffffff, s0, 2);
        s1 += __shfl_xor_sync(0xffffffff, s1, 1);
        s1 += __shfl_xor_sync(0xffffffff, s1, 2);
        if ((lane & 3) == 0) {
            atomicAdd(&g_sumexp[row],     s0);
            atomicAdd(&g_sumexp[row + 8], s1);
        }
    }
}

// ---------------------------------------------------------------------------
// Finalize: 4 blocks per row (vocab quarters); copy regions on quarter 3.
// Streaming loads/stores; argmax via packed u64 atomicMax; last arriving
// block publishes the prediction.
// ---------------------------------------------------------------------------
#define NQ 4
__global__ __launch_bounds__(256)
void finalize_kernel(const float* __restrict__ satt,
                     const float* __restrict__ tatt,
                     float* __restrict__ out) {
    const int row = blockIdx.y;
    const int q   = blockIdx.x;
    const int b   = row / NT;
    const int tid = threadIdx.x;

    __shared__ float red[256];
    __shared__ int   redi[256];
    __shared__ float src_acc[NSDV];
    __shared__ float tgt_acc[NTDV];

    const float pg    = g_p[row*3+2];
    const float scale = pg / g_sumexp[row];

    float* orow = out + (size_t)row * NOUT;
    float  bmax = -1.f;
    int    bidx = 0;

    if (q == 3) {
        const float pcs = g_p[row*3+0];
        const float pct = g_p[row*3+1];
        for (int i = tid; i < NSDV; i += 256) src_acc[i] = 0.f;
        for (int i = tid; i < NTDV; i += 256) tgt_acc[i] = 0.f;
        __syncthreads();
        for (int s = tid; s < NS; s += 256)
            atomicAdd(&src_acc[g_src_idx[b*NS + s]], satt[(size_t)row*NS + s]);
        for (int n = tid; n < NT; n += 256)
            atomicAdd(&tgt_acc[g_tgt_idx[b*NT + n]], tatt[(size_t)row*NTDV + n]);
        __syncthreads();
        for (int v = tid; v < NSDV; v += 256) {
            float pv = pcs * src_acc[v];
            __stcs(&orow[NV + v], pv);
            int gi = NV + v;
            if (pv > bmax || (pv == bmax && gi < bidx)) { bmax = pv; bidx = gi; }
        }
        for (int v = tid; v < NTDV; v += 256) {
            float pv = pct * tgt_acc[v];
            __stcs(&orow[NV + NSDV + v], pv);
            int gi = NV + NSDV + v;
            if (pv > bmax || (pv == bmax && gi < bidx)) { bmax = pv; bidx = gi; }
        }
    }

    // vocab quarter: [q*1000, (q+1)*1000) float4s
    const float4* srow4 = (const float4*)(g_scores + (size_t)row * NV);
    float4* orow4 = (float4*)orow;
    const int i0 = q * (NV/4/NQ);
    for (int i = i0 + tid; i < i0 + NV/4/NQ; i += 256) {
        float4 v = __ldcs(&srow4[i]);
        float4 p;
        p.x = __expf(v.x) * scale;
        p.y = __expf(v.y) * scale;
        p.z = __expf(v.z) * scale;
        p.w = __expf(v.w) * scale;
        if (i == 0) p.x = 0.f;
        __stcs(&orow4[i], p);
        int base = i * 4;
        if (p.x > bmax) { bmax = p.x; bidx = base;   }
        if (p.y > bmax) { bmax = p.y; bidx = base+1; }
        if (p.z > bmax) { bmax = p.z; bidx = base+2; }
        if (p.w > bmax) { bmax = p.w; bidx = base+3; }
    }

    red[tid]  = bmax;
    redi[tid] = bidx;
    __syncthreads();
    for (int o = 128; o > 0; o >>= 1) {
        if (tid < o) {
            float v2 = red[tid + o]; int i2 = redi[tid + o];
            if (v2 > red[tid] || (v2 == red[tid] && i2 < redi[tid])) {
                red[tid] = v2; redi[tid] = i2;
            }
        }
        __syncthreads();
    }
    if (tid == 0) {
        unsigned long long pk =
            ((unsigned long long)__float_as_uint(red[0]) << 32)
            | (unsigned long long)(0xFFFFFFFFu - (uint32_t)redi[0]);
        atomicMax(&g_amax[row], pk);
        __threadfence();
        int prev = atomicAdd(&g_done[row], 1);
        if (prev == NQ - 1) {   // last block for this row
            unsigned long long v = atomicAdd(&g_amax[row], 0ull);
            out[(size_t)MM * NOUT + row] =
                (float)(0xFFFFFFFFu - (uint32_t)v);
        }
    }
}

// ---------------------------------------------------------------------------
extern "C" void kernel_launch(void* const* d_in, const int* in_sizes, int n_in,
                              void* d_out, int out_size) {
    const float* hiddens = (const float*)d_in[0];
    const float* Wp      = (const float*)d_in[1];
    const float* bp      = (const float*)d_in[2];
    const float* Wv      = (const float*)d_in[3];
    const float* bv      = (const float*)d_in[4];
    const float* satt    = (const float*)d_in[5];
    const float* smap    = (const float*)d_in[6];
    const float* tatt    = (const float*)d_in[7];
    const float* tmap    = (const float*)d_in[8];
    float* out = (float*)d_out;

    cudaFuncSetAttribute(gemm_mma_kernel,
                         cudaFuncAttributeMaxDynamicSharedMemorySize, SMEM_GEMM);

    // gemm in launch slot 4 -> gets ncu-captured
    convB_kernel<<<dim3(NV/32, NH/32), dim3(32, 8)>>>(Wv);       // 1
    p_conv_kernel<<<MM/4, 128>>>(hiddens, Wp, bp);               // 2
    prep_idx_kernel<<<8, 256>>>(smap, tmap);                     // 3
    gemm_mma_kernel<<<dim3(NV/BN, MM/BM), 256, SMEM_GEMM>>>(bv); // 4
    finalize_kernel<<<dim3(NQ, MM), 256>>>(satt, tatt, out);     // 5
}

// round 13
// speedup vs baseline: 1.1595x; 1.0182x over previous
#include <cuda_runtime.h>
#include <cuda_bf16.h>
#include <cuda_fp16.h>
#include <math.h>
#include <stdint.h>

// Problem constants
#define NB   4
#define NT   512
#define NH   512
#define NV   32000
#define NS   512
#define NSDV 300
#define NTDV 512
#define MM   (NB*NT)              // 2048 rows
#define NOUT (NV+NSDV+NTDV)       // 32812
#define KK   (3*NH)               // 1536 expanded K (Ah|Ah|Al x Bh|Bl|Bh)

// Scratch (static device arrays; no allocation allowed)
__device__ __half g_scoresh[(size_t)MM*NV];       // 131 MB (fp16 scores)
__device__ float g_p[MM*3];
__device__ float g_sumexp[MM];
__device__ unsigned long long g_amax[MM];         // packed exact vocab argmax
__device__ int   g_src_idx[NB*NS];
__device__ int   g_tgt_idx[NB*NT];
__device__ __nv_bfloat16 g_Ap[(size_t)MM*KK];     // 6.3 MB  [m][k']
__device__ __nv_bfloat16 g_Bp[(size_t)NV*KK];     // 98 MB   [n][k'] (K-major)

// ---------------------------------------------------------------------------
__device__ __forceinline__ uint32_t smem_u32(const void* p) {
    uint32_t a;
    asm("{ .reg .u64 t; cvta.to.shared.u64 t, %1; cvt.u32.u64 %0, t; }"
        : "=r"(a) : "l"(p));
    return a;
}
__device__ __forceinline__ void cp_async16(uint32_t dst, const void* src) {
    asm volatile("cp.async.cg.shared.global [%0], [%1], 16;"
                 :: "r"(dst), "l"(src));
}
#define CP_COMMIT() asm volatile("cp.async.commit_group;")
#define CP_WAIT1()  asm volatile("cp.async.wait_group 1;")

__device__ __forceinline__ void ldmx4(uint32_t* r, uint32_t addr) {
    asm volatile("ldmatrix.sync.aligned.m8n8.x4.shared.b16 {%0,%1,%2,%3}, [%4];"
                 : "=r"(r[0]), "=r"(r[1]), "=r"(r[2]), "=r"(r[3]) : "r"(addr));
}
__device__ __forceinline__ void mma16816(float* c, const uint32_t* a,
                                         const uint32_t* b) {
    asm volatile(
        "mma.sync.aligned.m16n8k16.row.col.f32.bf16.bf16.f32 "
        "{%0,%1,%2,%3}, {%4,%5,%6,%7}, {%8,%9}, {%0,%1,%2,%3};"
        : "+f"(c[0]), "+f"(c[1]), "+f"(c[2]), "+f"(c[3])
        : "r"(a[0]), "r"(a[1]), "r"(a[2]), "r"(a[3]), "r"(b[0]), "r"(b[1]));
}

// order-preserving float -> uint key (works for all finite floats)
__device__ __forceinline__ uint32_t fkey(float v) {
    uint32_t b = __float_as_uint(v);
    return b ^ ((b & 0x80000000u) ? 0xFFFFFFFFu : 0x80000000u);
}
__device__ __forceinline__ float unfkey(uint32_t k) {
    uint32_t b = (k & 0x80000000u) ? (k ^ 0x80000000u) : ~k;
    return __uint_as_float(b);
}

// ---------------------------------------------------------------------------
// One-hot index extraction
// ---------------------------------------------------------------------------
__global__ void prep_idx_kernel(const float* __restrict__ smap,
                                const float* __restrict__ tmap) {
    int i = blockIdx.x * blockDim.x + threadIdx.x;   // 0..2047
    if (i >= NB*NS) return;
    {
        const float* r = smap + (size_t)i * NSDV;
        int idx = 0;
        for (int v = 0; v < NSDV; v++) if (r[v] > 0.5f) idx = v;
        g_src_idx[i] = idx;
    }
    {
        const float* r = tmap + (size_t)i * NTDV;
        int idx = 0;
        for (int v = 0; v < NTDV; v++) if (r[v] > 0.5f) idx = v;
        g_tgt_idx[i] = idx;
    }
}

// ---------------------------------------------------------------------------
// Merged: 3-way gate p = softmax(h@Wp+bp), A' = [Ah|Ah|Al] build,
// zero g_sumexp / g_amax. One warp per row.
// ---------------------------------------------------------------------------
__global__ void p_conv_kernel(const float* __restrict__ H,
                              const float* __restrict__ Wp,
                              const float* __restrict__ bp) {
    int warp = threadIdx.x >> 5;
    int lane = threadIdx.x & 31;
    int row  = blockIdx.x * 4 + warp;
    if (row >= MM) return;
    const float* h = H + (size_t)row * NH;
    __nv_bfloat16* ap = g_Ap + (size_t)row * KK;
    float s0 = 0.f, s1 = 0.f, s2 = 0.f;
    #pragma unroll
    for (int k = lane; k < NH; k += 32) {
        float hv = h[k];
        __nv_bfloat16 hi = __float2bfloat16(hv);
        __nv_bfloat16 lo = __float2bfloat16(hv - __bfloat162float(hi));
        ap[k]        = hi;
        ap[k + NH]   = hi;
        ap[k + 2*NH] = lo;
        s0 = fmaf(hv, Wp[k*3+0], s0);
        s1 = fmaf(hv, Wp[k*3+1], s1);
        s2 = fmaf(hv, Wp[k*3+2], s2);
    }
    #pragma unroll
    for (int o = 16; o > 0; o >>= 1) {
        s0 += __shfl_down_sync(0xffffffff, s0, o);
        s1 += __shfl_down_sync(0xffffffff, s1, o);
        s2 += __shfl_down_sync(0xffffffff, s2, o);
    }
    if (lane == 0) {
        g_sumexp[row] = 0.f;
        g_amax[row]   = 0ull;
        s0 += bp[0]; s1 += bp[1]; s2 += bp[2];
        float m = fmaxf(s0, fmaxf(s1, s2));
        float e0 = expf(s0 - m), e1 = expf(s1 - m), e2 = expf(s2 - m);
        float inv = 1.0f / (e0 + e1 + e2);
        g_p[row*3+0] = e0 * inv;
        g_p[row*3+1] = e1 * inv;
        g_p[row*3+2] = e2 * inv;
    }
}

// ---------------------------------------------------------------------------
// Transpose Wv [NH][NV] -> B' [NV][K'] = [Bh | Bl | Bh]
// ---------------------------------------------------------------------------
__global__ void convB_kernel(const float* __restrict__ Wv) {
    __shared__ float t[32][33];
    int n0 = blockIdx.x * 32, k0 = blockIdx.y * 32;
    int tx = threadIdx.x, ty = threadIdx.y;   // block (32, 8)
    #pragma unroll
    for (int i = 0; i < 32; i += 8)
        t[ty+i][tx] = Wv[(size_t)(k0 + ty + i) * NV + n0 + tx];   // t[k][n]
    __syncthreads();
    #pragma unroll
    for (int i = 0; i < 32; i += 8) {
        float v = t[tx][ty+i];                 // k = k0+tx, n = n0+ty+i
        __nv_bfloat16 hi = __float2bfloat16(v);
        __nv_bfloat16 lo = __float2bfloat16(v - __bfloat162float(hi));
        size_t base = (size_t)(n0 + ty + i) * KK + k0 + tx;
        g_Bp[base]        = hi;
        g_Bp[base + NH]   = lo;
        g_Bp[base + 2*NH] = hi;
    }
}

// ---------------------------------------------------------------------------
// mma.sync GEMM (R7 config): 128x128 tiles, BK=64, 3-stage cp.async,
// 8 warps of 32x64, strength-reduced addressing. Epilogue: fp16 score
// store + per-row sumexp + EXACT per-row vocab argmax (packed atomicMax).
// ---------------------------------------------------------------------------
#define BM 128
#define BN 128
#define BK 64
#define NKITER (KK/BK)        // 24
#define STAGE_B 32768         // A tile 16KB + B tile 16KB
#define SMEM_GEMM (3*STAGE_B) // 96 KB

__global__ __launch_bounds__(256, 2)
void gemm_mma_kernel(const float* __restrict__ bias) {
    extern __shared__ char smem[];
    const uint32_t sb = smem_u32(smem);
    const int tid  = threadIdx.x;
    const int w    = tid >> 5;
    const int lane = tid & 31;
    const int bm   = blockIdx.y * BM;    // 16
    const int bn   = blockIdx.x * BN;    // 250
    const int wm   = w & 3;              // warp row (4)
    const int wn   = w >> 2;             // warp col (2)

    float acc[2][8][4];
    #pragma unroll
    for (int i = 0; i < 2; i++)
        #pragma unroll
        for (int j = 0; j < 8; j++)
            #pragma unroll
            for (int q = 0; q < 4; q++) acc[i][j][q] = 0.f;

    // --- strength-reduced loader state ---
    const int lr = tid >> 3;             // 0..31
    const int lc = tid & 7;              // 16B chunk
    const __nv_bfloat16* aptr = g_Ap + (size_t)(bm + lr) * KK + lc * 8;
    const __nv_bfloat16* bptr = g_Bp + (size_t)(bn + lr) * KK + lc * 8;
    const uint32_t sw0 = (uint32_t)lr * 128 + (uint32_t)((lc ^ (lr & 7)) * 16);

#define LOAD_STAGE(s) do {                                                      \
    uint32_t d = sb + (uint32_t)(s) * STAGE_B + sw0;                            \
    _Pragma("unroll")                                                           \
    for (int i = 0; i < 4; i++) {                                               \
        cp_async16(d + i * 4096,         aptr + (size_t)i * 32 * KK);           \
        cp_async16(d + 16384 + i * 4096, bptr + (size_t)i * 32 * KK);           \
    }                                                                           \
    CP_COMMIT();                                                                \
    aptr += BK; bptr += BK;                                                     \
} while (0)

    // --- strength-reduced ldmatrix bases ---
    const uint32_t lnx = (uint32_t)(lane >> 4) * 16;
    uint32_t rp_a[2], rp_b[4];
    #pragma unroll
    for (int i = 0; i < 2; i++) {
        int row = wm * 32 + i * 16 + (lane & 15);
        rp_a[i] = (uint32_t)row * 128 + (lnx ^ (uint32_t)((row & 7) * 16));
    }
    #pragma unroll
    for (int jj = 0; jj < 4; jj++) {
        int row = wn * 64 + jj * 16 + (lane & 15);
        rp_b[jj] = (uint32_t)row * 128 + (lnx ^ (uint32_t)((row & 7) * 16));
    }

    LOAD_STAGE(0);
    LOAD_STAGE(1);

    for (int kt = 0; kt < NKITER; kt++) {
        const int s = kt % 3;
        CP_WAIT1();
        __syncthreads();
        if (kt + 2 < NKITER) LOAD_STAGE((kt + 2) % 3);

        const uint32_t abase = sb + (uint32_t)s * STAGE_B;
        const uint32_t bbase = abase + 16384;
        #pragma unroll
        for (int ks = 0; ks < 4; ks++) {
            const uint32_t kx = (uint32_t)ks << 5;
            uint32_t a[2][4];
            #pragma unroll
            for (int i = 0; i < 2; i++)
                ldmx4(a[i], abase + (rp_a[i] ^ kx));
            uint32_t b[8][2];
            #pragma unroll
            for (int jj = 0; jj < 4; jj++) {
                uint32_t r[4];
                ldmx4(r, bbase + (rp_b[jj] ^ kx));
                b[2*jj][0]   = r[0]; b[2*jj][1]   = r[2];
                b[2*jj+1][0] = r[1]; b[2*jj+1][1] = r[3];
            }
            #pragma unroll
            for (int i = 0; i < 2; i++)
                #pragma unroll
                for (int j = 0; j < 8; j++)
                    mma16816(acc[i][j], a[i], b[j]);
        }
    }

    // epilogue: bias add, fp16 store, per-row sumexp + exact vocab argmax
    #pragma unroll
    for (int i = 0; i < 2; i++) {
        const int row = bm + wm * 32 + i * 16 + (lane >> 2);
        float s0 = 0.f, s1 = 0.f;            // sumexp: rows row, row+8
        float m0 = -INFINITY, m1 = -INFINITY;
        int   c0 = 1, c1 = 1;
        #pragma unroll
        for (int j = 0; j < 8; j++) {
            const int col = bn + wn * 64 + j * 8 + (lane & 3) * 2;
            const float b0 = bias[col], b1 = bias[col + 1];
            float v00 = acc[i][j][0] + b0, v01 = acc[i][j][1] + b1;
            float v10 = acc[i][j][2] + b0, v11 = acc[i][j][3] + b1;
            *(__half2*)(g_scoresh + (size_t)row * NV + col)
                = __floats2half2_rn(v00, v01);
            *(__half2*)(g_scoresh + (size_t)(row + 8) * NV + col)
                = __floats2half2_rn(v10, v11);
            bool nz = (col != 0);
            s0 += (nz ? __expf(v00) : 0.f) + __expf(v01);
            s1 += (nz ? __expf(v10) : 0.f) + __expf(v11);
            if (nz && v00 > m0) { m0 = v00; c0 = col; }
            if (v01 > m0)       { m0 = v01; c0 = col + 1; }
            if (nz && v10 > m1) { m1 = v10; c1 = col; }
            if (v11 > m1)       { m1 = v11; c1 = col + 1; }
        }
        #pragma unroll
        for (int o = 1; o <= 2; o <<= 1) {
            s0 += __shfl_xor_sync(0xffffffff, s0, o);
            s1 += __shfl_xor_sync(0xffffffff, s1, o);
            float mo0 = __shfl_xor_sync(0xffffffff, m0, o);
            int   co0 = __shfl_xor_sync(0xffffffff, c0, o);
            if (mo0 > m0 || (mo0 == m0 && co0 < c0)) { m0 = mo0; c0 = co0; }
            float mo1 = __shfl_xor_sync(0xffffffff, m1, o);
            int   co1 = __shfl_xor_sync(0xffffffff, c1, o);
            if (mo1 > m1 || (mo1 == m1 && co1 < c1)) { m1 = mo1; c1 = co1; }
        }
        if ((lane & 3) == 0) {
            atomicAdd(&g_sumexp[row],     s0);
            atomicAdd(&g_sumexp[row + 8], s1);
            unsigned long long p0 =
                ((unsigned long long)fkey(m0) << 32)
                | (unsigned long long)(0xFFFFFFFFu - (uint32_t)c0);
            unsigned long long p1 =
                ((unsigned long long)fkey(m1) << 32)
                | (unsigned long long)(0xFFFFFFFFu - (uint32_t)c1);
            atomicMax(&g_amax[row],     p0);
            atomicMax(&g_amax[row + 8], p1);
        }
    }
}

// ---------------------------------------------------------------------------
// Finalize: grid (NQ+1, MM). q<NQ: pure-streaming vocab prob write from
// fp16 scores. q==NQ: copy-region scatter + write + final argmax using the
// exact vocab max from the GEMM.
// ---------------------------------------------------------------------------
#define NQ 2
__global__ __launch_bounds__(256)
void finalize_kernel(const float* __restrict__ satt,
                     const float* __restrict__ tatt,
                     float* __restrict__ out) {
    const int row = blockIdx.y;
    const int q   = blockIdx.x;
    const int tid = threadIdx.x;

    const float pg    = g_p[row*3+2];
    const float scale = pg / g_sumexp[row];
    float* orow = out + (size_t)row * NOUT;

    if (q < NQ) {
        // vocab slice: 8 halves (16B) per iteration, pure streaming
        const uint4* s4 = (const uint4*)(g_scoresh + (size_t)row * NV);
        float4* orow4 = (float4*)orow;
        const int i0 = q * (NV/8/NQ);
        for (int i = i0 + tid; i < i0 + NV/8/NQ; i += 256) {
            uint4 u = __ldcs(&s4[i]);
            float2 a0 = __half22float2(*(__half2*)&u.x);
            float2 a1 = __half22float2(*(__half2*)&u.y);
            float2 a2 = __half22float2(*(__half2*)&u.z);
            float2 a3 = __half22float2(*(__half2*)&u.w);
            float4 p0, p1;
            p0.x = __expf(a0.x) * scale;  p0.y = __expf(a0.y) * scale;
            p0.z = __expf(a1.x) * scale;  p0.w = __expf(a1.y) * scale;
            p1.x = __expf(a2.x) * scale;  p1.y = __expf(a2.y) * scale;
            p1.z = __expf(a3.x) * scale;  p1.w = __expf(a3.y) * scale;
            if (i == 0) p0.x = 0.f;      // masked vocab index 0
            __stcs(&orow4[2*i],     p0);
            __stcs(&orow4[2*i + 1], p1);
        }
        return;
    }

    // copy-region block
    __shared__ float red[256];
    __shared__ int   redi[256];
    __shared__ float src_acc[NSDV];
    __shared__ float tgt_acc[NTDV];
    const int b = row / NT;
    const float pcs = g_p[row*3+0];
    const float pct = g_p[row*3+1];

    for (int i = tid; i < NSDV; i += 256) src_acc[i] = 0.f;
    for (int i = tid; i < NTDV; i += 256) tgt_acc[i] = 0.f;
    __syncthreads();
    for (int s = tid; s < NS; s += 256)
        atomicAdd(&src_acc[g_src_idx[b*NS + s]], satt[(size_t)row*NS + s]);
    for (int n = tid; n < NT; n += 256)
        atomicAdd(&tgt_acc[g_tgt_idx[b*NT + n]], tatt[(size_t)row*NTDV + n]);
    __syncthreads();

    float bmax = -1.f;
    int   bidx = NOUT;
    for (int v = tid; v < NSDV; v += 256) {
        float pv = pcs * src_acc[v];
        __stcs(&orow[NV + v], pv);
        int gi = NV + v;
        if (pv > bmax || (pv == bmax && gi < bidx)) { bmax = pv; bidx = gi; }
    }
    for (int v = tid; v < NTDV; v += 256) {
        float pv = pct * tgt_acc[v];
        __stcs(&orow[NV + NSDV + v], pv);
        int gi = NV + NSDV + v;
        if (pv > bmax || (pv == bmax && gi < bidx)) { bmax = pv; bidx = gi; }
    }

    red[tid]  = bmax;
    redi[tid] = bidx;
    __syncthreads();
    for (int o = 128; o > 0; o >>= 1) {
        if (tid < o) {
            float v2 = red[tid + o]; int i2 = redi[tid + o];
            if (v2 > red[tid] || (v2 == red[tid] && i2 < redi[tid])) {
                red[tid] = v2; redi[tid] = i2;
            }
        }
        __syncthreads();
    }
    if (tid == 0) {
        // exact vocab max from the GEMM epilogue
        unsigned long long pk = g_amax[row];
        float vmax  = __expf(unfkey((uint32_t)(pk >> 32))) * scale;
        int   vidx  = (int)(0xFFFFFFFFu - (uint32_t)pk);
        float cmax  = red[0];
        int   cidx  = redi[0];
        int   pred  = (cmax > vmax || (cmax == vmax && cidx < vidx))
                        ? cidx : vidx;
        out[(size_t)MM * NOUT + row] = (float)pred;
    }
}

// ---------------------------------------------------------------------------
extern "C" void kernel_launch(void* const* d_in, const int* in_sizes, int n_in,
                              void* d_out, int out_size) {
    const float* hiddens = (const float*)d_in[0];
    const float* Wp      = (const float*)d_in[1];
    const float* bp      = (const float*)d_in[2];
    const float* Wv      = (const float*)d_in[3];
    const float* bv      = (const float*)d_in[4];
    const float* satt    = (const float*)d_in[5];
    const float* smap    = (const float*)d_in[6];
    const float* tatt    = (const float*)d_in[7];
    const float* tmap    = (const float*)d_in[8];
    float* out = (float*)d_out;

    cudaFuncSetAttribute(gemm_mma_kernel,
                         cudaFuncAttributeMaxDynamicSharedMemorySize, SMEM_GEMM);

    // gemm in launch slot 4 -> gets ncu-captured
    convB_kernel<<<dim3(NV/32, NH/32), dim3(32, 8)>>>(Wv);       // 1
    p_conv_kernel<<<MM/4, 128>>>(hiddens, Wp, bp);               // 2
    prep_idx_kernel<<<8, 256>>>(smap, tmap);                     // 3
    gemm_mma_kernel<<<dim3(NV/BN, MM/BM), 256, SMEM_GEMM>>>(bv); // 4
    finalize_kernel<<<dim3(NQ + 1, MM), 256>>>(satt, tatt, out); // 5
}